// round 17
// baseline (speedup 1.0000x reference)
#include <cuda_runtime.h>
#include <math.h>

// ---------------------------------------------------------------------------
// RadiomicsPreservationLoss — R8 rolling+pipelined stencil over LONG balanced
// contiguous row-runs (R9 schedule): priming once per ~18-row run instead of
// once per 4 rows. Steady state: 3 LDG.128/row (img x2 + mask), prefetch
// distance 1 row, 3-slot ring. occ-3, 444 blocks, fused last-block finalize.
// inputs: input_img, output_img, roi_mask  [32,1,512,512] f32
// output: [intensity, texture, shape, total] (4 x f32)
// ---------------------------------------------------------------------------

#define HH 512
#define WW 512
#define BB 32
#define NBLK 444                 // 3 blocks/SM
#define NTHR 256
#define NSLOTS (NBLK * 8)        // 3552 warp slots
#define RU 65536                 // 128 stripcols * 512 rows
#define RUQ (RU / NSLOTS)        // 18
#define RUR (RU % NSLOTS)        // 1600
#define FULLM 0xffffffffu

__device__ double g_part[NBLK][11];
__device__ unsigned g_cnt = 0;

// Load one row as 6 values: 4 own cols + left halo (cb-1) + right halo (cb+4).
// p points at (row, cb); ok = row in image. Shuffles for interior lane edges,
// predicated LDG for strip edges (<=2 lanes), zeros outside the image.
__device__ __forceinline__ void ldrow(
    float* __restrict__ R, const float* __restrict__ p, bool ok,
    bool hasL, bool hasR, int lane)
{
    float4 q = make_float4(0.f, 0.f, 0.f, 0.f);
    if (ok) q = *(const float4*)p;
    R[0] = q.x; R[1] = q.y; R[2] = q.z; R[3] = q.w;

    float al = __shfl_up_sync(FULLM, q.w, 1);
    float ar = __shfl_down_sync(FULLM, q.x, 1);
    float al_e = (lane == 0  && ok && hasL) ? p[-1] : 0.f;
    float ar_e = (lane == 31 && ok && hasR) ? p[4]  : 0.f;
    R[4] = (lane == 0)  ? al_e : al;
    R[5] = (lane == 31) ? ar_e : ar;
}

// 3x3 variance, laplacian, center for 4 cols from three rolled 6-wide rows.
__device__ __forceinline__ void proc6(
    const float* __restrict__ Ap, const float* __restrict__ Ac,
    const float* __restrict__ An,
    float* __restrict__ var, float* __restrict__ lap, float* __restrict__ cen)
{
    float cs[6], cq[6];
    #pragma unroll
    for (int j = 0; j < 6; j++) {
        cs[j] = Ap[j] + Ac[j] + An[j];
        float u = Ap[j] * Ap[j];
        u = fmaf(Ac[j], Ac[j], u);
        cq[j] = fmaf(An[j], An[j], u);
    }
    const float inv9 = 1.f / 9.f;
    #pragma unroll
    for (int p = 0; p < 4; p++) {
        float Sm = (p == 0) ? cs[4] : cs[p - 1];
        float Sp = (p == 3) ? cs[5] : cs[p + 1];
        float Qm = (p == 0) ? cq[4] : cq[p - 1];
        float Qp = (p == 3) ? cq[5] : cq[p + 1];
        float S = Sm + cs[p] + Sp;
        float Q = Qm + cq[p] + Qp;
        float bmn = S * inv9;
        var[p] = fmaf(-bmn, bmn, Q * inv9);
        float am = (p == 0) ? Ac[4] : Ac[p - 1];
        float ap = (p == 3) ? Ac[5] : Ac[p + 1];
        lap[p] = fmaf(-5.f, Ac[p], cs[p] + am + ap);
        cen[p] = Ac[p];
    }
}

__global__ void __launch_bounds__(NTHR, 3) k_main(
    const float* __restrict__ g_in,
    const float* __restrict__ g_out,
    const float* __restrict__ g_mask,
    float* __restrict__ final_out)
{
    __shared__ float sred[11][8];
    __shared__ bool s_last;
    __shared__ double sacc[11];

    const int t    = threadIdx.x;
    const int lane = t & 31;
    const int wid  = t >> 5;
    const int slot = blockIdx.x * 8 + wid;   // 0..3551

    float msum = 0.f;
    float xi1 = 0.f, xi2 = 0.f, xi3 = 0.f, xi4 = 0.f;
    float yo1 = 0.f, yo2 = 0.f, yo3 = 0.f, yo4 = 0.f;
    float texs = 0.f, shps = 0.f;

    int u = slot * RUQ + min(slot, RUR);
    const int uend = u + RUQ + (slot < RUR ? 1 : 0);

    const float4 z4 = make_float4(0.f, 0.f, 0.f, 0.f);

    while (u < uend) {
        const int scol  = u >> 9;            // stripcol 0..127
        const int ra    = u & 511;           // first output row of this run
        const int n     = min(uend - u, HH - ra);
        const int img   = scol >> 2;
        const int strip = scol & 3;
        const int cb    = (strip << 7) + lane * 4;
        const bool hasL = (strip > 0);
        const bool hasR = (strip < 3);

        const size_t base = (size_t)img * (HH * WW) + (size_t)ra * WW + cb;
        const float* pi = g_in   + base;     // walks with current row r
        const float* po = g_out  + base;
        const float* pm = g_mask + base;

        // ---- prime the 3-slot ring: rows ra-1, ra, ra+1 + mask row ra ----
        float Pi[3][6], Po[3][6];
        ldrow(Pi[0], pi - WW, ra > 0,      hasL, hasR, lane);
        ldrow(Po[0], po - WW, ra > 0,      hasL, hasR, lane);
        ldrow(Pi[1], pi,      true,        hasL, hasR, lane);
        ldrow(Po[1], po,      true,        hasL, hasR, lane);
        ldrow(Pi[2], pi + WW, ra + 1 < HH, hasL, hasR, lane);
        ldrow(Po[2], po + WW, ra + 1 < HH, hasL, hasR, lane);
        float4 Mcur = *(const float4*)pm;
        int r = ra;

#define STEP(A, B, C)                                                        \
    do {                                                                     \
        float Fi[6], Fo[6];                                                  \
        const bool okn = (r + 2 < HH);                                       \
        ldrow(Fi, pi + 2 * WW, okn, hasL, hasR, lane);                       \
        ldrow(Fo, po + 2 * WW, okn, hasL, hasR, lane);                       \
        float4 mnx = (r + 1 < HH) ? *(const float4*)(pm + WW) : z4;          \
        float vi[4], li[4], xc[4];                                           \
        proc6(Pi[A], Pi[B], Pi[C], vi, li, xc);                              \
        float vo[4], lo[4], yc[4];                                           \
        proc6(Po[A], Po[B], Po[C], vo, lo, yc);                              \
        float mv[4] = { Mcur.x, Mcur.y, Mcur.z, Mcur.w };                    \
        _Pragma("unroll")                                                    \
        for (int j = 0; j < 4; j++) {                                        \
            float m = mv[j];                                                 \
            msum += m;                                                       \
            float x = xc[j], y = yc[j];                                      \
            float x2 = x * x, y2 = y * y;                                    \
            float qx = x2 * m, qy = y2 * m;                                  \
            xi1 = fmaf(x, m, xi1);  xi2 += qx;                               \
            xi3 = fmaf(x, qx, xi3); xi4 = fmaf(x2, qx, xi4);                 \
            yo1 = fmaf(y, m, yo1);  yo2 += qy;                               \
            yo3 = fmaf(y, qy, yo3); yo4 = fmaf(y2, qy, yo4);                 \
            texs = fmaf(fabsf(vo[j] - vi[j]), m, texs);                      \
            shps = fmaf(fabsf(lo[j] - li[j]), m, shps);                      \
        }                                                                    \
        _Pragma("unroll")                                                    \
        for (int j = 0; j < 6; j++) { Pi[A][j] = Fi[j]; Po[A][j] = Fo[j]; }  \
        Mcur = mnx;                                                          \
        pi += WW; po += WW; pm += WW; r++;                                   \
    } while (0)

        int k = 0;
        while (k + 3 <= n) { STEP(0, 1, 2); STEP(1, 2, 0); STEP(2, 0, 1); k += 3; }
        if (k < n) { STEP(0, 1, 2); k++; }
        if (k < n) { STEP(1, 2, 0); k++; }
#undef STEP

        u += n;
    }

    // ---- block reduction -> fp64 partial ----
    float acc[11] = { msum, xi1, xi2, xi3, xi4, yo1, yo2, yo3, yo4, texs, shps };
    #pragma unroll
    for (int k = 0; k < 11; k++) {
        float v = acc[k];
        #pragma unroll
        for (int off = 16; off; off >>= 1)
            v += __shfl_xor_sync(FULLM, v, off);
        if (lane == 0) sred[k][wid] = v;
    }
    __syncthreads();
    if (t < 11) {
        double s = 0.0;
        #pragma unroll
        for (int w = 0; w < 8; w++) s += (double)sred[t][w];
        g_part[blockIdx.x][t] = s;
    }

    // ---- last-block finalize ----
    __threadfence();
    if (t == 0) {
        unsigned prev = atomicAdd(&g_cnt, 1u);
        s_last = (prev == NBLK - 1);
    }
    __syncthreads();
    if (!s_last) return;

    for (int k = wid; k < 11; k += 8) {
        double s = 0.0;
        for (int b = lane; b < NBLK; b += 32)
            s += g_part[b][k];
        #pragma unroll
        for (int off = 16; off; off >>= 1)
            s += __shfl_xor_sync(FULLM, s, off);
        if (lane == 0) sacc[k] = s;
    }
    __syncthreads();

    if (t == 0) {
        g_cnt = 0;   // reset for next graph replay
        const double EPS = 1e-8;
        const double NTOT = (double)BB * HH * WW;

        double M0 = sacc[0];
        double ms = M0 + EPS;
        double Mi1 = sacc[1], Mi2 = sacc[2], Mi3 = sacc[3], Mi4 = sacc[4];
        double Mo1 = sacc[5], Mo2 = sacc[6], Mo3 = sacc[7], Mo4 = sacc[8];

        double im = Mi1 / ms, om = Mo1 / ms;
        double im2 = im * im, om2 = om * om;

        double c2i = Mi2 - 2.0 * im * Mi1 + im2 * M0;
        double c3i = Mi3 - 3.0 * im * Mi2 + 3.0 * im2 * Mi1 - im2 * im * M0;
        double c4i = Mi4 - 4.0 * im * Mi3 + 6.0 * im2 * Mi2 - 4.0 * im2 * im * Mi1 + im2 * im2 * M0;

        double c2o = Mo2 - 2.0 * om * Mo1 + om2 * M0;
        double c3o = Mo3 - 3.0 * om * Mo2 + 3.0 * om2 * Mo1 - om2 * om * M0;
        double c4o = Mo4 - 4.0 * om * Mo3 + 6.0 * om2 * Mo2 - 4.0 * om2 * om * Mo1 + om2 * om2 * M0;

        double iv = c2i / ms, ov = c2o / ms;
        double isk = c3i / (ms * (iv * sqrt(iv) + EPS));
        double osk = c3o / (ms * (ov * sqrt(ov) + EPS));
        double iku = c4i / (ms * (iv * iv + EPS));
        double oku = c4o / (ms * (ov * ov + EPS));

        double dm = im - om, dv = iv - ov, dsk = isk - osk, dku = iku - oku;
        double inten = dm * dm + dv * dv + dsk * dsk + dku * dku;
        double tex = sacc[9]  / NTOT;
        double shp = sacc[10] / NTOT;
        double total = inten + tex + 0.5 * shp;

        final_out[0] = (float)inten;
        final_out[1] = (float)tex;
        final_out[2] = (float)shp;
        final_out[3] = (float)total;
    }
}

extern "C" void kernel_launch(void* const* d_in, const int* in_sizes, int n_in,
                              void* d_out, int out_size) {
    const float* in_img  = (const float*)d_in[0];
    const float* out_img = (const float*)d_in[1];
    const float* mask    = (const float*)d_in[2];

    k_main<<<NBLK, NTHR>>>(in_img, out_img, mask, (float*)d_out);
}